// round 1
// baseline (speedup 1.0000x reference)
#include <cuda_runtime.h>
#include <math.h>

#define BB   8
#define NN   4096      // 64*64 tokens
#define CC   256
#define CIN  64
#define DHX  1024
#define MM   (BB*NN)   // 32768

// ---------------- scratch (device globals, no runtime alloc) ----------------
__device__ float g_h   [MM*CC];
__device__ float g_psi [MM*CC];
__device__ float g_bufA[MM*CC];
__device__ float g_bufB[MM*CC];
__device__ float g_bufC[MM*CC];
__device__ float g_num [MM*CC];
__device__ float g_U   [MM*CC];
__device__ float g_he  [MM*DHX];
__device__ float g_hg  [MM*DHX];
__device__ float g_kvT [BB*CC*CC];
__device__ float g_ksum[BB*CC];
__device__ float g_pool[BB*CC];
__device__ float g_sgt [BB*CC];

// ---------------- small device helpers ----------------
__device__ __forceinline__ float siluf(float x) { return x / (1.f + expf(-x)); }
__device__ __forceinline__ float sigm(float x)  { return 1.f / (1.f + expf(-x)); }
__device__ __forceinline__ float geluf(float x) {
    float x3 = x * x * x;
    return 0.5f * x * (1.f + tanhf(0.7978845608028654f * (x + 0.044715f * x3)));
}

// ---------------- zero ----------------
__global__ void zero_kernel(float* p, int n) {
    int i = blockIdx.x * 256 + threadIdx.x;
    if (i < n) p[i] = 0.f;
}

// ---------------- in_proj: h[b,n,o] = silu( sum_c x[b,c,n] * w[o,c] ) --------
__global__ __launch_bounds__(256) void in_proj_kernel(
    const float* __restrict__ x, const float* __restrict__ w, float* __restrict__ h)
{
    __shared__ float Xs[64][65];
    __shared__ float Ws[64][65];
    int b = blockIdx.z, n0 = blockIdx.x * 64, o0 = blockIdx.y * 64;
    int t = threadIdx.x;
#pragma unroll
    for (int i = 0; i < 4; i++) {
        int id = t + i * 256;
        int r  = id >> 4;            // row (c for X, o for W)
        int q  = (id & 15) * 4;      // col quad
        float4 vx = *(const float4*)(x + ((long)b * CIN + r) * NN + n0 + q);
        Xs[r][q] = vx.x; Xs[r][q+1] = vx.y; Xs[r][q+2] = vx.z; Xs[r][q+3] = vx.w;
        float4 vw = *(const float4*)(w + (o0 + r) * CIN + q);
        Ws[q][r] = vw.x; Ws[q+1][r] = vw.y; Ws[q+2][r] = vw.z; Ws[q+3][r] = vw.w;
    }
    __syncthreads();
    int tx = t % 16, ty = t / 16;    // tx -> o, ty -> n
    float acc[4][4] = {};
#pragma unroll
    for (int c = 0; c < 64; c++) {
        float fn[4], fo[4];
#pragma unroll
        for (int i = 0; i < 4; i++) fn[i] = Xs[c][ty*4 + i];
#pragma unroll
        for (int j = 0; j < 4; j++) fo[j] = Ws[c][tx*4 + j];
#pragma unroll
        for (int i = 0; i < 4; i++)
#pragma unroll
            for (int j = 0; j < 4; j++) acc[i][j] += fn[i] * fo[j];
    }
#pragma unroll
    for (int i = 0; i < 4; i++) {
        int n = n0 + ty*4 + i;
        float4 r;
        r.x = siluf(acc[i][0]); r.y = siluf(acc[i][1]);
        r.z = siluf(acc[i][2]); r.w = siluf(acc[i][3]);
        *(float4*)(h + ((long)b * NN + n) * CC + o0 + tx*4) = r;
    }
}

// ---------------- depthwise 3x3 conv (+sigmoid or +gelu) ----------------
template<int CH, int ACT>
__global__ void dwconv_kernel(const float* __restrict__ in, const float* __restrict__ cw,
                              const float* __restrict__ cb, float* __restrict__ outp)
{
    long i = (long)blockIdx.x * 256 + threadIdx.x;
    int c   = (int)(i % CH);
    long pix = i / CH;
    int hw  = (int)(pix & (NN - 1));
    int b   = (int)(pix >> 12);
    int hh  = hw >> 6, ww = hw & 63;
    float acc = cb[c];
    const float* base = in + ((long)b * NN) * CH + c;
#pragma unroll
    for (int ky = 0; ky < 3; ky++) {
        int hy = hh + ky - 1;
        if ((unsigned)hy >= 64u) continue;
#pragma unroll
        for (int kx = 0; kx < 3; kx++) {
            int wx = ww + kx - 1;
            if ((unsigned)wx >= 64u) continue;
            acc += base[(long)(hy * 64 + wx) * CH] * cw[c * 9 + ky * 3 + kx];
        }
    }
    outp[i] = ACT ? geluf(acc) : sigm(acc);
}

// ---------------- generic SGEMM: Out[M,N] = A[M,K] @ W[N,K]^T (+bias)(+2*aux)
template<int MODE>
__global__ __launch_bounds__(256) void sgemm_kernel(
    const float* __restrict__ A, const float* __restrict__ Wt,
    const float* __restrict__ bias, const float* __restrict__ aux,
    float* __restrict__ Out, int Mdim, int Ndim, int Kdim,
    long aStrideB, long wStrideB, long oStrideB)
{
    int bz = blockIdx.z;
    A   += (long)bz * aStrideB;
    Wt  += (long)bz * wStrideB;
    Out += (long)bz * oStrideB;
    __shared__ float As[16][128];
    __shared__ float Bs[16][128];
    int m0 = blockIdx.y * 128, n0 = blockIdx.x * 128;
    int t = threadIdx.x;
    int tx = t % 16, ty = t / 16;
    float acc[8][8] = {};
    for (int k0 = 0; k0 < Kdim; k0 += 16) {
#pragma unroll
        for (int i = 0; i < 2; i++) {
            int id = t + i * 256;
            int m  = id >> 2;
            int kq = (id & 3) * 4;
            float4 v = *(const float4*)(A + (long)(m0 + m) * Kdim + k0 + kq);
            As[kq+0][m] = v.x; As[kq+1][m] = v.y; As[kq+2][m] = v.z; As[kq+3][m] = v.w;
            float4 w = *(const float4*)(Wt + (long)(n0 + m) * Kdim + k0 + kq);
            Bs[kq+0][m] = w.x; Bs[kq+1][m] = w.y; Bs[kq+2][m] = w.z; Bs[kq+3][m] = w.w;
        }
        __syncthreads();
#pragma unroll
        for (int k = 0; k < 16; k++) {
            float4 a0 = *(const float4*)&As[k][ty*8];
            float4 a1 = *(const float4*)&As[k][ty*8+4];
            float4 b0 = *(const float4*)&Bs[k][tx*8];
            float4 b1 = *(const float4*)&Bs[k][tx*8+4];
            float fa[8] = {a0.x,a0.y,a0.z,a0.w,a1.x,a1.y,a1.z,a1.w};
            float fb[8] = {b0.x,b0.y,b0.z,b0.w,b1.x,b1.y,b1.z,b1.w};
#pragma unroll
            for (int i = 0; i < 8; i++)
#pragma unroll
                for (int j = 0; j < 8; j++) acc[i][j] += fa[i] * fb[j];
        }
        __syncthreads();
    }
#pragma unroll
    for (int i = 0; i < 8; i++) {
        int m = m0 + ty*8 + i;
#pragma unroll
        for (int j = 0; j < 8; j++) {
            int n = n0 + tx*8 + j;
            float v = acc[i][j];
            if (bias) v += bias[n];
            if (MODE == 1) v += 2.f * aux[(long)m * Ndim + n];
            Out[(long)m * Ndim + n] = v;
        }
    }
}

// ---------------- phi: apply pos-emb + psi gate + relu^2 to Q,K in place ----
__global__ void phi_kernel(const float* __restrict__ psi,
                           float* __restrict__ qb, float* __restrict__ kb)
{
    int i = blockIdx.x * 256 + threadIdx.x;
    int c   = i & 255;
    int pix = i >> 8;
    int hw  = pix & (NN - 1);
    int hh  = hw >> 6, ww = hw & 63;
    int grp = c >> 6, ci = c & 63;
    float omega = expf(-(float)ci * (9.210340371976184f / 64.f));
    float coord = (grp < 2) ? (float)ww : (float)hh;
    float arg = coord * omega;
    float posv = ((grp & 1) == 0) ? sinf(arg) : cosf(arg);
    float ps = psi[i];
    float q = ps * (qb[i] + posv); q = fmaxf(q, 0.f); qb[i] = q * q;
    float k = ps * (kb[i] + posv); k = fmaxf(k, 0.f); kb[i] = k * k;
}

// ---------------- pool: sum over 256-pixel chunks per channel (atomic) ------
__global__ void pool_kernel(const float* __restrict__ in, float* __restrict__ outp)
{
    int t = threadIdx.x;
    long base = (long)blockIdx.x * 256;      // pixel base
    int b = blockIdx.x >> 4;                  // 16 chunks per batch
    float acc = 0.f;
    for (int p = 0; p < 256; p++) acc += in[(base + p) * CC + t];
    atomicAdd(&outp[b * CC + t], acc);
}

// ---------------- kv^T: kvT[b,d,c] = sum_n phiK[b,n,c] * V[b,n,d] (split-K) -
__global__ __launch_bounds__(256) void kv_kernel(
    const float* __restrict__ phiK, const float* __restrict__ V, float* __restrict__ kvT)
{
    __shared__ float Ks[16][64];
    __shared__ float Vs[16][64];
    int b = blockIdx.z >> 2;
    int split = blockIdx.z & 3;
    int c0 = blockIdx.x * 64, d0 = blockIdx.y * 64;
    int t = threadIdx.x;
    int tx = t % 16, ty = t / 16;
    const float* Kp = phiK + (long)b * NN * CC;
    const float* Vp = V    + (long)b * NN * CC;
    int kr = t >> 4, cq = (t & 15) * 4;
    float acc[4][4] = {};
    int nend = split * 1024 + 1024;
    for (int n0 = split * 1024; n0 < nend; n0 += 16) {
        *(float4*)&Ks[kr][cq] = *(const float4*)(Kp + (long)(n0 + kr) * CC + c0 + cq);
        *(float4*)&Vs[kr][cq] = *(const float4*)(Vp + (long)(n0 + kr) * CC + d0 + cq);
        __syncthreads();
#pragma unroll
        for (int k = 0; k < 16; k++) {
            float4 fc = *(const float4*)&Ks[k][tx*4];
            float4 fd = *(const float4*)&Vs[k][ty*4];
            float fcv[4] = {fc.x, fc.y, fc.z, fc.w};
            float fdv[4] = {fd.x, fd.y, fd.z, fd.w};
#pragma unroll
            for (int j = 0; j < 4; j++)
#pragma unroll
                for (int i2 = 0; i2 < 4; i2++) acc[j][i2] += fdv[j] * fcv[i2];
        }
        __syncthreads();
    }
#pragma unroll
    for (int j = 0; j < 4; j++)
#pragma unroll
        for (int i2 = 0; i2 < 4; i2++)
            atomicAdd(&kvT[(long)b * CC * CC + (long)(d0 + ty*4 + j) * CC + c0 + tx*4 + i2],
                      acc[j][i2]);
}

// ---------------- den = phiQ . ksum + eps ; num /= den ----------------------
__global__ void dendiv_kernel(const float* __restrict__ phiQ,
                              const float* __restrict__ ksum, float* __restrict__ num)
{
    int warp = threadIdx.x >> 5, lane = threadIdx.x & 31;
    long pix = (long)blockIdx.x * 8 + warp;
    int b = (int)(pix >> 12);
    float s = 0.f;
#pragma unroll
    for (int k = 0; k < 8; k++) {
        int c = lane + k * 32;
        s += phiQ[pix * CC + c] * ksum[b * CC + c];
    }
#pragma unroll
    for (int off = 16; off; off >>= 1) s += __shfl_xor_sync(0xffffffffu, s, off);
    float inv = 1.f / (s + 1e-5f);
#pragma unroll
    for (int k = 0; k < 8; k++) {
        int c = lane + k * 32;
        num[pix * CC + c] *= inv;
    }
}

// ---------------- DyT: tanh(g*(x-mu)/(std_ddof1+eps) + b) -------------------
__global__ void dyt_kernel(const float* __restrict__ in1, const float* __restrict__ in2,
                           const float* __restrict__ gam, const float* __restrict__ bet,
                           float* __restrict__ outp)
{
    int warp = threadIdx.x >> 5, lane = threadIdx.x & 31;
    long pix = (long)blockIdx.x * 8 + warp;
    float v[8];
    float s = 0.f, sq = 0.f;
#pragma unroll
    for (int k = 0; k < 8; k++) {
        int c = lane + k * 32;
        float x = in1[pix * CC + c];
        if (in2) x += in2[pix * CC + c];
        v[k] = x; s += x; sq += x * x;
    }
#pragma unroll
    for (int off = 16; off; off >>= 1) {
        s  += __shfl_xor_sync(0xffffffffu, s,  off);
        sq += __shfl_xor_sync(0xffffffffu, sq, off);
    }
    float mu  = s * (1.f / 256.f);
    float var = fmaxf(sq - 256.f * mu * mu, 0.f) * (1.f / 255.f);
    float sd  = sqrtf(var) + 1e-5f;
    float inv = 1.f / sd;
#pragma unroll
    for (int k = 0; k < 8; k++) {
        int c = lane + k * 32;
        outp[pix * CC + c] = tanhf(gam[c] * (v[k] - mu) * inv + bet[c]);
    }
}

// ---------------- Mona FC: s = sigmoid( (pool/N) @ mw^T + mb ) --------------
__global__ void monafc_kernel(const float* __restrict__ pool,
                              const float* __restrict__ mw, const float* __restrict__ mb,
                              float* __restrict__ sgate)
{
    int b = blockIdx.x, o = threadIdx.x;
    float acc = mb[o];
    const float invN = 1.f / (float)NN;
    for (int c = 0; c < CC; c++)
        acc += pool[b * CC + c] * invN * mw[o * CC + c];
    sgate[b * CC + o] = sigm(acc);
}

// ---------------- gate: x *= s[b,c] ----------------------------------------
__global__ void gate_kernel(float* __restrict__ p, const float* __restrict__ sgate)
{
    long i = (long)blockIdx.x * 256 + threadIdx.x;
    int c = (int)(i & 255);
    long pix = i >> 8;
    int b = (int)(pix >> 12);
    p[i] *= sgate[b * CC + c];
}

// ---------------- out_proj: out[b,o,n] = silu( sum_c Y[b,n,c]*w[o,c] ) ------
__global__ __launch_bounds__(256) void out_proj_kernel(
    const float* __restrict__ Y, const float* __restrict__ w, float* __restrict__ outp)
{
    __shared__ float Ys[64][65];
    __shared__ float Ws[64][65];
    int b = blockIdx.z, n0 = blockIdx.x * 64;
    int t = threadIdx.x;
    int tx = t % 16, ty = t / 16;   // tx -> n, ty -> o
    float acc[4][4] = {};           // [o][n]
    for (int ck = 0; ck < CC; ck += 64) {
#pragma unroll
        for (int i = 0; i < 4; i++) {
            int id = t + i * 256;
            int r  = id >> 4;        // n for Y, o for W
            int cq = (id & 15) * 4;
            float4 vy = *(const float4*)(Y + ((long)b * NN + n0 + r) * CC + ck + cq);
            Ys[cq][r] = vy.x; Ys[cq+1][r] = vy.y; Ys[cq+2][r] = vy.z; Ys[cq+3][r] = vy.w;
            float4 vw = *(const float4*)(w + r * CC + ck + cq);
            Ws[cq][r] = vw.x; Ws[cq+1][r] = vw.y; Ws[cq+2][r] = vw.z; Ws[cq+3][r] = vw.w;
        }
        __syncthreads();
#pragma unroll
        for (int c = 0; c < 64; c++) {
            float fn[4], fo[4];
#pragma unroll
            for (int i = 0; i < 4; i++) fn[i] = Ys[c][tx*4 + i];
#pragma unroll
            for (int j = 0; j < 4; j++) fo[j] = Ws[c][ty*4 + j];
#pragma unroll
            for (int j = 0; j < 4; j++)
#pragma unroll
                for (int i = 0; i < 4; i++) acc[j][i] += fo[j] * fn[i];
        }
        __syncthreads();
    }
#pragma unroll
    for (int j = 0; j < 4; j++) {
        int o = ty*4 + j;
        float4 r;
        r.x = siluf(acc[j][0]); r.y = siluf(acc[j][1]);
        r.z = siluf(acc[j][2]); r.w = siluf(acc[j][3]);
        *(float4*)(outp + ((long)b * 64 + o) * NN + n0 + tx*4) = r;
    }
}

// ---------------- launch ----------------------------------------------------
extern "C" void kernel_launch(void* const* d_in, const int* in_sizes, int n_in,
                              void* d_out, int out_size)
{
    const float* x         = (const float*)d_in[0];
    const float* in_proj_w = (const float*)d_in[1];
    const float* wq_w = (const float*)d_in[2];  const float* wq_b = (const float*)d_in[3];
    const float* wk_w = (const float*)d_in[4];  const float* wk_b = (const float*)d_in[5];
    const float* wv_w = (const float*)d_in[6];  const float* wv_b = (const float*)d_in[7];
    const float* wo_w = (const float*)d_in[8];  const float* wo_b = (const float*)d_in[9];
    const float* psi_w = (const float*)d_in[10]; const float* psi_b = (const float*)d_in[11];
    const float* dyt_g = (const float*)d_in[12]; const float* dyt_b = (const float*)d_in[13];
    const float* m1_w = (const float*)d_in[14]; const float* m1_b = (const float*)d_in[15];
    const float* m2_w = (const float*)d_in[16]; const float* m2_b = (const float*)d_in[17];
    const float* we_w = (const float*)d_in[18]; const float* we_b = (const float*)d_in[19];
    const float* dw_w = (const float*)d_in[20]; const float* dw_b = (const float*)d_in[21];
    const float* wp_w = (const float*)d_in[22]; const float* wp_b = (const float*)d_in[23];
    const float* out_proj_w = (const float*)d_in[24];
    float* outp = (float*)d_out;

    float *p_h, *p_psi, *p_A, *p_B, *p_C, *p_num, *p_U, *p_he, *p_hg;
    float *p_kvT, *p_ksum, *p_pool, *p_s;
    cudaGetSymbolAddress((void**)&p_h,    g_h);
    cudaGetSymbolAddress((void**)&p_psi,  g_psi);
    cudaGetSymbolAddress((void**)&p_A,    g_bufA);
    cudaGetSymbolAddress((void**)&p_B,    g_bufB);
    cudaGetSymbolAddress((void**)&p_C,    g_bufC);
    cudaGetSymbolAddress((void**)&p_num,  g_num);
    cudaGetSymbolAddress((void**)&p_U,    g_U);
    cudaGetSymbolAddress((void**)&p_he,   g_he);
    cudaGetSymbolAddress((void**)&p_hg,   g_hg);
    cudaGetSymbolAddress((void**)&p_kvT,  g_kvT);
    cudaGetSymbolAddress((void**)&p_ksum, g_ksum);
    cudaGetSymbolAddress((void**)&p_pool, g_pool);
    cudaGetSymbolAddress((void**)&p_s,    g_sgt);

    // zero accumulators
    zero_kernel<<<(BB*CC*CC + 255) / 256, 256>>>(p_kvT, BB*CC*CC);
    zero_kernel<<<(BB*CC + 255) / 256, 256>>>(p_ksum, BB*CC);

    // 1) in_proj + SiLU -> h  [B,N,C]
    in_proj_kernel<<<dim3(NN/64, CC/64, BB), 256>>>(x, in_proj_w, p_h);

    // 2) psi = sigmoid(dwconv3x3(h))
    dwconv_kernel<CC, 0><<<MM*CC/256, 256>>>(p_h, psi_w, psi_b, p_psi);

    // 3) Q/K/V linear projections
    sgemm_kernel<0><<<dim3(CC/128, MM/128, 1), 256>>>(p_h, wq_w, wq_b, nullptr, p_A, MM, CC, CC, 0, 0, 0);
    sgemm_kernel<0><<<dim3(CC/128, MM/128, 1), 256>>>(p_h, wk_w, wk_b, nullptr, p_B, MM, CC, CC, 0, 0, 0);
    sgemm_kernel<0><<<dim3(CC/128, MM/128, 1), 256>>>(p_h, wv_w, wv_b, nullptr, p_C, MM, CC, CC, 0, 0, 0);

    // 4) phiQ, phiK in place
    phi_kernel<<<MM*CC/256, 256>>>(p_psi, p_A, p_B);

    // 5) ksum = sum_n phiK
    pool_kernel<<<BB*16, 256>>>(p_B, p_ksum);

    // 6) kvT[b,d,c] (split-K over n with atomics)
    kv_kernel<<<dim3(CC/64, CC/64, BB*4), 256>>>(p_B, p_C, p_kvT);

    // 7) num = phiQ @ kvT^T (batched)
    sgemm_kernel<0><<<dim3(CC/128, NN/128, BB), 256>>>(p_A, p_kvT, nullptr, nullptr, p_num,
                                                       NN, CC, CC, (long)NN*CC, (long)CC*CC, (long)NN*CC);

    // 8) num /= (phiQ . ksum + eps)
    dendiv_kernel<<<MM/8, 256>>>(p_A, p_ksum, p_num);

    // 9) attn = num @ wo^T + b  -> bufC
    sgemm_kernel<0><<<dim3(CC/128, MM/128, 1), 256>>>(p_num, wo_w, wo_b, nullptr, p_C, MM, CC, CC, 0, 0, 0);

    // 10) T1 = DyT(h + attn)
    dyt_kernel<<<MM/8, 256>>>(p_h, p_C, dyt_g, dyt_b, p_U);

    // 11) Mona 1
    zero_kernel<<<(BB*CC + 255) / 256, 256>>>(p_pool, BB*CC);
    pool_kernel<<<BB*16, 256>>>(p_U, p_pool);
    monafc_kernel<<<BB, 256>>>(p_pool, m1_w, m1_b, p_s);
    gate_kernel<<<MM*CC/256, 256>>>(p_U, p_s);          // U1 in g_U

    // 12) EDFFN
    sgemm_kernel<0><<<dim3(DHX/128, MM/128, 1), 256>>>(p_U, we_w, we_b, nullptr, p_he, MM, DHX, CC, 0, 0, 0);
    dwconv_kernel<DHX, 1><<<MM*DHX/256, 256>>>(p_he, dw_w, dw_b, p_hg);
    // U2 = 2*U1 + (hg @ wp^T + b)
    sgemm_kernel<1><<<dim3(CC/128, MM/128, 1), 256>>>(p_hg, wp_w, wp_b, p_U, p_A, MM, CC, DHX, 0, 0, 0);

    // 13) T2 = DyT(U2), Mona 2
    dyt_kernel<<<MM/8, 256>>>(p_A, nullptr, dyt_g, dyt_b, p_U);
    zero_kernel<<<(BB*CC + 255) / 256, 256>>>(p_pool, BB*CC);
    pool_kernel<<<BB*16, 256>>>(p_U, p_pool);
    monafc_kernel<<<BB, 256>>>(p_pool, m2_w, m2_b, p_s);
    gate_kernel<<<MM*CC/256, 256>>>(p_U, p_s);          // Y in g_U

    // 14) out_proj + SiLU -> [B,64,H,W]
    out_proj_kernel<<<dim3(NN/64, 1, BB), 256>>>(p_U, out_proj_w, outp);
}

// round 2
// speedup vs baseline: 2.1885x; 2.1885x over previous
#include <cuda_runtime.h>
#include <math.h>
#include <stdint.h>

#define BB   8
#define NN   4096      // 64*64 tokens
#define CC   256
#define CIN  64
#define DHX  1024
#define MM   (BB*NN)   // 32768

// ---------------- scratch (device globals, no runtime alloc) ----------------
__device__ float g_h   [MM*CC];
__device__ float g_psi [MM*CC];
__device__ float g_bufA[MM*CC];
__device__ float g_bufB[MM*CC];
__device__ float g_bufC[MM*CC];
__device__ float g_num [MM*CC];
__device__ float g_U   [MM*CC];
__device__ float g_he  [MM*DHX];
__device__ float g_hg  [MM*DHX];
__device__ float g_kvT [BB*CC*CC];
__device__ float g_ksum[BB*CC];
__device__ float g_pool[BB*CC];
__device__ float g_sgt [BB*CC];
__device__ float g_psiT[9*CC];
__device__ float g_dwT [9*DHX];

// ---------------- small device helpers ----------------
__device__ __forceinline__ float siluf(float x) { return x / (1.f + expf(-x)); }
__device__ __forceinline__ float sigm(float x)  { return 1.f / (1.f + expf(-x)); }
__device__ __forceinline__ float geluf(float x) {
    float x3 = x * x * x;
    return 0.5f * x * (1.f + tanhf(0.7978845608028654f * (x + 0.044715f * x3)));
}
__device__ __forceinline__ uint32_t tf32cvt(float f) {
    uint32_t u; asm("cvt.rna.tf32.f32 %0, %1;" : "=r"(u) : "f"(f)); return u;
}
__device__ __forceinline__ void mma_tf32(float* c, const uint32_t* a, const uint32_t* b) {
    asm volatile("mma.sync.aligned.m16n8k8.row.col.f32.tf32.tf32.f32 "
        "{%0,%1,%2,%3}, {%4,%5,%6,%7}, {%8,%9}, {%0,%1,%2,%3};"
        : "+f"(c[0]), "+f"(c[1]), "+f"(c[2]), "+f"(c[3])
        : "r"(a[0]), "r"(a[1]), "r"(a[2]), "r"(a[3]), "r"(b[0]), "r"(b[1]));
}

// ---------------- zero ----------------
__global__ void zero_kernel(float* p, int n) {
    int i = blockIdx.x * 256 + threadIdx.x;
    if (i < n) p[i] = 0.f;
}

// ---------------- weight transpose [C][9] -> [9][C] ----------------
__global__ void wtrans_kernel(const float* __restrict__ w, float* __restrict__ wT, int CH) {
    int i = blockIdx.x * 256 + threadIdx.x;
    if (i < CH * 9) { int c = i / 9, t = i % 9; wT[t * CH + c] = w[i]; }
}

// ---------------- in_proj: h[b,n,o] = silu( sum_c x[b,c,n] * w[o,c] ) --------
__global__ __launch_bounds__(256) void in_proj_kernel(
    const float* __restrict__ x, const float* __restrict__ w, float* __restrict__ h)
{
    __shared__ float Xs[64][65];
    __shared__ float Ws[64][65];
    int b = blockIdx.z, n0 = blockIdx.x * 64, o0 = blockIdx.y * 64;
    int t = threadIdx.x;
#pragma unroll
    for (int i = 0; i < 4; i++) {
        int id = t + i * 256;
        int r  = id >> 4;
        int q  = (id & 15) * 4;
        float4 vx = *(const float4*)(x + ((long)b * CIN + r) * NN + n0 + q);
        Xs[r][q] = vx.x; Xs[r][q+1] = vx.y; Xs[r][q+2] = vx.z; Xs[r][q+3] = vx.w;
        float4 vw = *(const float4*)(w + (o0 + r) * CIN + q);
        Ws[q][r] = vw.x; Ws[q+1][r] = vw.y; Ws[q+2][r] = vw.z; Ws[q+3][r] = vw.w;
    }
    __syncthreads();
    int tx = t % 16, ty = t / 16;
    float acc[4][4] = {};
#pragma unroll
    for (int c = 0; c < 64; c++) {
        float fn[4], fo[4];
#pragma unroll
        for (int i = 0; i < 4; i++) fn[i] = Xs[c][ty*4 + i];
#pragma unroll
        for (int j = 0; j < 4; j++) fo[j] = Ws[c][tx*4 + j];
#pragma unroll
        for (int i = 0; i < 4; i++)
#pragma unroll
            for (int j = 0; j < 4; j++) acc[i][j] += fn[i] * fo[j];
    }
#pragma unroll
    for (int i = 0; i < 4; i++) {
        int n = n0 + ty*4 + i;
        float4 r;
        r.x = siluf(acc[i][0]); r.y = siluf(acc[i][1]);
        r.z = siluf(acc[i][2]); r.w = siluf(acc[i][3]);
        *(float4*)(h + ((long)b * NN + n) * CC + o0 + tx*4) = r;
    }
}

// ---------------- depthwise 3x3 conv, float4 channels, transposed weights ----
template<int CH, int ACT>
__global__ void dwconv4_kernel(const float* __restrict__ in, const float* __restrict__ cwT,
                               const float* __restrict__ cb, float* __restrict__ outp)
{
    const int CG = CH / 4;
    long i = (long)blockIdx.x * 256 + threadIdx.x;    // float4 group index
    int c4  = (int)(i % CG);
    long pix = i / CG;
    int hw  = (int)(pix & (NN - 1));
    int b   = (int)(pix >> 12);
    int hh  = hw >> 6, ww = hw & 63;
    int c = c4 * 4;
    float4 bias4 = *(const float4*)(cb + c);
    float ax = bias4.x, ay = bias4.y, az = bias4.z, aw = bias4.w;
    const float* base = in + ((long)b * NN) * CH + c;
#pragma unroll
    for (int ky = 0; ky < 3; ky++) {
        int hy = hh + ky - 1;
        if ((unsigned)hy >= 64u) continue;
#pragma unroll
        for (int kx = 0; kx < 3; kx++) {
            int wx = ww + kx - 1;
            if ((unsigned)wx >= 64u) continue;
            float4 v = *(const float4*)(base + (long)(hy * 64 + wx) * CH);
            float4 w = *(const float4*)(cwT + (ky * 3 + kx) * CH + c);
            ax += v.x * w.x; ay += v.y * w.y; az += v.z * w.z; aw += v.w * w.w;
        }
    }
    float4 r;
    if (ACT) { r.x = geluf(ax); r.y = geluf(ay); r.z = geluf(az); r.w = geluf(aw); }
    else     { r.x = sigm(ax);  r.y = sigm(ay);  r.z = sigm(az);  r.w = sigm(aw);  }
    *(float4*)(outp + i * 4) = r;
}

// ---------------- TF32 MMA GEMM: Out[M,N] = A[M,K] @ Wt[N,K]^T (+bias)(+2aux)
// CTA tile 128x128, k-tile 32, 8 warps in 2(M)x4(N), warp tile 64x32.
template<int MODE>
__global__ __launch_bounds__(256) void mma_gemm(
    const float* __restrict__ A, const float* __restrict__ Wt,
    const float* __restrict__ bias, const float* __restrict__ aux,
    float* __restrict__ Out, int Ndim, int Kdim,
    long aStrideB, long wStrideB, long oStrideB)
{
    __shared__ uint32_t As[128][36];
    __shared__ uint32_t Bs[128][36];
    int bz = blockIdx.z;
    A   += (long)bz * aStrideB;
    Wt  += (long)bz * wStrideB;
    Out += (long)bz * oStrideB;
    int m0 = blockIdx.y * 128, n0 = blockIdx.x * 128;
    int tid = threadIdx.x, wid = tid >> 5, l = tid & 31;
    int wm = (wid >> 2) * 64, wn = (wid & 3) * 32;
    int lg = l >> 2, lt = l & 3;          // groupID, threadID_in_group
    float acc[4][4][4] = {};
    for (int k0 = 0; k0 < Kdim; k0 += 32) {
#pragma unroll
        for (int i = 0; i < 4; i++) {
            int id = tid + i * 256;
            int r  = id >> 3;
            int cq = (id & 7) * 4;
            float4 va = *(const float4*)(A + (long)(m0 + r) * Kdim + k0 + cq);
            uint4 ua; ua.x = tf32cvt(va.x); ua.y = tf32cvt(va.y);
                      ua.z = tf32cvt(va.z); ua.w = tf32cvt(va.w);
            *(uint4*)&As[r][cq] = ua;
            float4 vb = *(const float4*)(Wt + (long)(n0 + r) * Kdim + k0 + cq);
            uint4 ub; ub.x = tf32cvt(vb.x); ub.y = tf32cvt(vb.y);
                      ub.z = tf32cvt(vb.z); ub.w = tf32cvt(vb.w);
            *(uint4*)&Bs[r][cq] = ub;
        }
        __syncthreads();
#pragma unroll
        for (int ks = 0; ks < 4; ks++) {
            int kk = ks * 8;
            uint32_t af[4][4], bf[4][2];
#pragma unroll
            for (int mi = 0; mi < 4; mi++) {
                int rb = wm + mi * 16 + lg;
                af[mi][0] = As[rb][kk + lt];
                af[mi][1] = As[rb + 8][kk + lt];
                af[mi][2] = As[rb][kk + 4 + lt];
                af[mi][3] = As[rb + 8][kk + 4 + lt];
            }
#pragma unroll
            for (int ni = 0; ni < 4; ni++) {
                int rb = wn + ni * 8 + lg;
                bf[ni][0] = Bs[rb][kk + lt];
                bf[ni][1] = Bs[rb][kk + 4 + lt];
            }
#pragma unroll
            for (int mi = 0; mi < 4; mi++)
#pragma unroll
                for (int ni = 0; ni < 4; ni++)
                    mma_tf32(acc[mi][ni], af[mi], bf[ni]);
        }
        __syncthreads();
    }
#pragma unroll
    for (int mi = 0; mi < 4; mi++) {
        int r0 = m0 + wm + mi * 16 + lg;
        int r1 = r0 + 8;
#pragma unroll
        for (int ni = 0; ni < 4; ni++) {
            int c = n0 + wn + ni * 8 + lt * 2;
            float v0 = acc[mi][ni][0], v1 = acc[mi][ni][1];
            float v2 = acc[mi][ni][2], v3 = acc[mi][ni][3];
            if (bias) { v0 += bias[c]; v1 += bias[c+1]; v2 += bias[c]; v3 += bias[c+1]; }
            if (MODE == 1) {
                v0 += 2.f * aux[(long)r0 * Ndim + c];
                v1 += 2.f * aux[(long)r0 * Ndim + c + 1];
                v2 += 2.f * aux[(long)r1 * Ndim + c];
                v3 += 2.f * aux[(long)r1 * Ndim + c + 1];
            }
            Out[(long)r0 * Ndim + c]     = v0;
            Out[(long)r0 * Ndim + c + 1] = v1;
            Out[(long)r1 * Ndim + c]     = v2;
            Out[(long)r1 * Ndim + c + 1] = v3;
        }
    }
}

// ---------------- kvT[b,d,c] = sum_n V[b,n,d] * phiK[b,n,c], TF32 MMA -------
// [k][m] smem layout gives free transpose in the fragment loads. split-K x8.
__global__ __launch_bounds__(256) void kv_mma(
    const float* __restrict__ phiK, const float* __restrict__ V, float* __restrict__ kvT)
{
    __shared__ uint32_t Vs[32][132];
    __shared__ uint32_t Ks[32][132];
    int b = blockIdx.z >> 3, split = blockIdx.z & 7;
    int d0 = blockIdx.y * 128, c0 = blockIdx.x * 128;
    const float* Vp = V    + (long)b * NN * CC;
    const float* Kp = phiK + (long)b * NN * CC;
    int tid = threadIdx.x, wid = tid >> 5, l = tid & 31;
    int wm = (wid >> 2) * 64, wn = (wid & 3) * 32;
    int lg = l >> 2, lt = l & 3;
    float acc[4][4][4] = {};
    int nend = split * 512 + 512;
    for (int n0 = split * 512; n0 < nend; n0 += 32) {
#pragma unroll
        for (int i = 0; i < 4; i++) {
            int id = tid + i * 256;
            int nl = id >> 5;
            int q  = (id & 31) * 4;
            float4 v = *(const float4*)(Vp + (long)(n0 + nl) * CC + d0 + q);
            uint4 uv; uv.x = tf32cvt(v.x); uv.y = tf32cvt(v.y);
                      uv.z = tf32cvt(v.z); uv.w = tf32cvt(v.w);
            *(uint4*)&Vs[nl][q] = uv;
            float4 k = *(const float4*)(Kp + (long)(n0 + nl) * CC + c0 + q);
            uint4 uk; uk.x = tf32cvt(k.x); uk.y = tf32cvt(k.y);
                      uk.z = tf32cvt(k.z); uk.w = tf32cvt(k.w);
            *(uint4*)&Ks[nl][q] = uk;
        }
        __syncthreads();
#pragma unroll
        for (int ks = 0; ks < 4; ks++) {
            int kk = ks * 8;
            uint32_t af[4][4], bf[4][2];
#pragma unroll
            for (int mi = 0; mi < 4; mi++) {
                int rb = wm + mi * 16;
                af[mi][0] = Vs[kk + lt][rb + lg];
                af[mi][1] = Vs[kk + lt][rb + 8 + lg];
                af[mi][2] = Vs[kk + 4 + lt][rb + lg];
                af[mi][3] = Vs[kk + 4 + lt][rb + 8 + lg];
            }
#pragma unroll
            for (int ni = 0; ni < 4; ni++) {
                int cb = wn + ni * 8;
                bf[ni][0] = Ks[kk + lt][cb + lg];
                bf[ni][1] = Ks[kk + 4 + lt][cb + lg];
            }
#pragma unroll
            for (int mi = 0; mi < 4; mi++)
#pragma unroll
                for (int ni = 0; ni < 4; ni++)
                    mma_tf32(acc[mi][ni], af[mi], bf[ni]);
        }
        __syncthreads();
    }
    long base = (long)b * CC * CC;
#pragma unroll
    for (int mi = 0; mi < 4; mi++) {
        int r0 = d0 + wm + mi * 16 + lg;
        int r1 = r0 + 8;
#pragma unroll
        for (int ni = 0; ni < 4; ni++) {
            int c = c0 + wn + ni * 8 + lt * 2;
            atomicAdd(&kvT[base + (long)r0 * CC + c],     acc[mi][ni][0]);
            atomicAdd(&kvT[base + (long)r0 * CC + c + 1], acc[mi][ni][1]);
            atomicAdd(&kvT[base + (long)r1 * CC + c],     acc[mi][ni][2]);
            atomicAdd(&kvT[base + (long)r1 * CC + c + 1], acc[mi][ni][3]);
        }
    }
}

// ---------------- phi: apply pos-emb + psi gate + relu^2 to Q,K in place ----
__global__ void phi_kernel(const float* __restrict__ psi,
                           float* __restrict__ qb, float* __restrict__ kb)
{
    int i = blockIdx.x * 256 + threadIdx.x;
    int c   = i & 255;
    int pix = i >> 8;
    int hw  = pix & (NN - 1);
    int hh  = hw >> 6, ww = hw & 63;
    int grp = c >> 6, ci = c & 63;
    float omega = expf(-(float)ci * (9.210340371976184f / 64.f));
    float coord = (grp < 2) ? (float)ww : (float)hh;
    float arg = coord * omega;
    float posv = ((grp & 1) == 0) ? sinf(arg) : cosf(arg);
    float ps = psi[i];
    float q = ps * (qb[i] + posv); q = fmaxf(q, 0.f); qb[i] = q * q;
    float k = ps * (kb[i] + posv); k = fmaxf(k, 0.f); kb[i] = k * k;
}

// ---------------- pool: sum over 256-pixel chunks per channel (atomic) ------
__global__ void pool_kernel(const float* __restrict__ in, float* __restrict__ outp)
{
    int t = threadIdx.x;
    long base = (long)blockIdx.x * 256;
    int b = blockIdx.x >> 4;
    float acc = 0.f;
    for (int p = 0; p < 256; p++) acc += in[(base + p) * CC + t];
    atomicAdd(&outp[b * CC + t], acc);
}

// ---------------- den = phiQ . ksum + eps ; num /= den ----------------------
__global__ void dendiv_kernel(const float* __restrict__ phiQ,
                              const float* __restrict__ ksum, float* __restrict__ num)
{
    int warp = threadIdx.x >> 5, lane = threadIdx.x & 31;
    long pix = (long)blockIdx.x * 8 + warp;
    int b = (int)(pix >> 12);
    float s = 0.f;
#pragma unroll
    for (int k = 0; k < 8; k++) {
        int c = lane + k * 32;
        s += phiQ[pix * CC + c] * ksum[b * CC + c];
    }
#pragma unroll
    for (int off = 16; off; off >>= 1) s += __shfl_xor_sync(0xffffffffu, s, off);
    float inv = 1.f / (s + 1e-5f);
#pragma unroll
    for (int k = 0; k < 8; k++) {
        int c = lane + k * 32;
        num[pix * CC + c] *= inv;
    }
}

// ---------------- DyT: tanh(g*(x-mu)/(std_ddof1+eps) + b) -------------------
__global__ void dyt_kernel(const float* __restrict__ in1, const float* __restrict__ in2,
                           const float* __restrict__ gam, const float* __restrict__ bet,
                           float* __restrict__ outp)
{
    int warp = threadIdx.x >> 5, lane = threadIdx.x & 31;
    long pix = (long)blockIdx.x * 8 + warp;
    float v[8];
    float s = 0.f, sq = 0.f;
#pragma unroll
    for (int k = 0; k < 8; k++) {
        int c = lane + k * 32;
        float x = in1[pix * CC + c];
        if (in2) x += in2[pix * CC + c];
        v[k] = x; s += x; sq += x * x;
    }
#pragma unroll
    for (int off = 16; off; off >>= 1) {
        s  += __shfl_xor_sync(0xffffffffu, s,  off);
        sq += __shfl_xor_sync(0xffffffffu, sq, off);
    }
    float mu  = s * (1.f / 256.f);
    float var = fmaxf(sq - 256.f * mu * mu, 0.f) * (1.f / 255.f);
    float sd  = sqrtf(var) + 1e-5f;
    float inv = 1.f / sd;
#pragma unroll
    for (int k = 0; k < 8; k++) {
        int c = lane + k * 32;
        outp[pix * CC + c] = tanhf(gam[c] * (v[k] - mu) * inv + bet[c]);
    }
}

// ---------------- Mona FC: s = sigmoid( (pool/N) @ mw^T + mb ) --------------
__global__ void monafc_kernel(const float* __restrict__ pool,
                              const float* __restrict__ mw, const float* __restrict__ mb,
                              float* __restrict__ sgate)
{
    int b = blockIdx.x, o = threadIdx.x;
    float acc = mb[o];
    const float invN = 1.f / (float)NN;
    for (int c = 0; c < CC; c++)
        acc += pool[b * CC + c] * invN * mw[o * CC + c];
    sgate[b * CC + o] = sigm(acc);
}

// ---------------- gate: x *= s[b,c] ----------------------------------------
__global__ void gate_kernel(float* __restrict__ p, const float* __restrict__ sgate)
{
    long i = (long)blockIdx.x * 256 + threadIdx.x;
    int c = (int)(i & 255);
    long pix = i >> 8;
    int b = (int)(pix >> 12);
    p[i] *= sgate[b * CC + c];
}

// ---------------- out_proj: out[b,o,n] = silu( sum_c Y[b,n,c]*w[o,c] ) ------
__global__ __launch_bounds__(256) void out_proj_kernel(
    const float* __restrict__ Y, const float* __restrict__ w, float* __restrict__ outp)
{
    __shared__ float Ys[64][65];
    __shared__ float Ws[64][65];
    int b = blockIdx.z, n0 = blockIdx.x * 64;
    int t = threadIdx.x;
    int tx = t % 16, ty = t / 16;
    float acc[4][4] = {};
    for (int ck = 0; ck < CC; ck += 64) {
#pragma unroll
        for (int i = 0; i < 4; i++) {
            int id = t + i * 256;
            int r  = id >> 4;
            int cq = (id & 15) * 4;
            float4 vy = *(const float4*)(Y + ((long)b * NN + n0 + r) * CC + ck + cq);
            Ys[cq][r] = vy.x; Ys[cq+1][r] = vy.y; Ys[cq+2][r] = vy.z; Ys[cq+3][r] = vy.w;
            float4 vw = *(const float4*)(w + r * CC + ck + cq);
            Ws[cq][r] = vw.x; Ws[cq+1][r] = vw.y; Ws[cq+2][r] = vw.z; Ws[cq+3][r] = vw.w;
        }
        __syncthreads();
#pragma unroll
        for (int c = 0; c < 64; c++) {
            float fn[4], fo[4];
#pragma unroll
            for (int i = 0; i < 4; i++) fn[i] = Ys[c][tx*4 + i];
#pragma unroll
            for (int j = 0; j < 4; j++) fo[j] = Ws[c][ty*4 + j];
#pragma unroll
            for (int j = 0; j < 4; j++)
#pragma unroll
                for (int i = 0; i < 4; i++) acc[j][i] += fo[j] * fn[i];
        }
        __syncthreads();
    }
#pragma unroll
    for (int j = 0; j < 4; j++) {
        int o = ty*4 + j;
        float4 r;
        r.x = siluf(acc[j][0]); r.y = siluf(acc[j][1]);
        r.z = siluf(acc[j][2]); r.w = siluf(acc[j][3]);
        *(float4*)(outp + ((long)b * 64 + o) * NN + n0 + tx*4) = r;
    }
}

// ---------------- launch ----------------------------------------------------
extern "C" void kernel_launch(void* const* d_in, const int* in_sizes, int n_in,
                              void* d_out, int out_size)
{
    const float* x         = (const float*)d_in[0];
    const float* in_proj_w = (const float*)d_in[1];
    const float* wq_w = (const float*)d_in[2];  const float* wq_b = (const float*)d_in[3];
    const float* wk_w = (const float*)d_in[4];  const float* wk_b = (const float*)d_in[5];
    const float* wv_w = (const float*)d_in[6];  const float* wv_b = (const float*)d_in[7];
    const float* wo_w = (const float*)d_in[8];  const float* wo_b = (const float*)d_in[9];
    const float* psi_w = (const float*)d_in[10]; const float* psi_b = (const float*)d_in[11];
    const float* dyt_g = (const float*)d_in[12]; const float* dyt_b = (const float*)d_in[13];
    const float* m1_w = (const float*)d_in[14]; const float* m1_b = (const float*)d_in[15];
    const float* m2_w = (const float*)d_in[16]; const float* m2_b = (const float*)d_in[17];
    const float* we_w = (const float*)d_in[18]; const float* we_b = (const float*)d_in[19];
    const float* dw_w = (const float*)d_in[20]; const float* dw_b = (const float*)d_in[21];
    const float* wp_w = (const float*)d_in[22]; const float* wp_b = (const float*)d_in[23];
    const float* out_proj_w = (const float*)d_in[24];
    float* outp = (float*)d_out;

    float *p_h, *p_psi, *p_A, *p_B, *p_C, *p_num, *p_U, *p_he, *p_hg;
    float *p_kvT, *p_ksum, *p_pool, *p_s, *p_psiT, *p_dwT;
    cudaGetSymbolAddress((void**)&p_h,    g_h);
    cudaGetSymbolAddress((void**)&p_psi,  g_psi);
    cudaGetSymbolAddress((void**)&p_A,    g_bufA);
    cudaGetSymbolAddress((void**)&p_B,    g_bufB);
    cudaGetSymbolAddress((void**)&p_C,    g_bufC);
    cudaGetSymbolAddress((void**)&p_num,  g_num);
    cudaGetSymbolAddress((void**)&p_U,    g_U);
    cudaGetSymbolAddress((void**)&p_he,   g_he);
    cudaGetSymbolAddress((void**)&p_hg,   g_hg);
    cudaGetSymbolAddress((void**)&p_kvT,  g_kvT);
    cudaGetSymbolAddress((void**)&p_ksum, g_ksum);
    cudaGetSymbolAddress((void**)&p_pool, g_pool);
    cudaGetSymbolAddress((void**)&p_s,    g_sgt);
    cudaGetSymbolAddress((void**)&p_psiT, g_psiT);
    cudaGetSymbolAddress((void**)&p_dwT,  g_dwT);

    // prep: zero accumulators, transpose dwconv weights
    zero_kernel<<<(BB*CC*CC + 255) / 256, 256>>>(p_kvT, BB*CC*CC);
    zero_kernel<<<(BB*CC + 255) / 256, 256>>>(p_ksum, BB*CC);
    wtrans_kernel<<<(CC*9 + 255) / 256, 256>>>(psi_w, p_psiT, CC);
    wtrans_kernel<<<(DHX*9 + 255) / 256, 256>>>(dw_w, p_dwT, DHX);

    // 1) in_proj + SiLU -> h  [B,N,C]
    in_proj_kernel<<<dim3(NN/64, CC/64, BB), 256>>>(x, in_proj_w, p_h);

    // 2) psi = sigmoid(dwconv3x3(h))
    dwconv4_kernel<CC, 0><<<MM*(CC/4)/256, 256>>>(p_h, p_psiT, psi_b, p_psi);

    // 3) Q/K/V linear projections (tensor cores)
    mma_gemm<0><<<dim3(CC/128, MM/128, 1), 256>>>(p_h, wq_w, wq_b, nullptr, p_A, CC, CC, 0, 0, 0);
    mma_gemm<0><<<dim3(CC/128, MM/128, 1), 256>>>(p_h, wk_w, wk_b, nullptr, p_B, CC, CC, 0, 0, 0);
    mma_gemm<0><<<dim3(CC/128, MM/128, 1), 256>>>(p_h, wv_w, wv_b, nullptr, p_C, CC, CC, 0, 0, 0);

    // 4) phiQ, phiK in place
    phi_kernel<<<MM*CC/256, 256>>>(p_psi, p_A, p_B);

    // 5) ksum = sum_n phiK
    pool_kernel<<<BB*16, 256>>>(p_B, p_ksum);

    // 6) kvT[b,d,c] (tensor cores, split-K over n with atomics)
    kv_mma<<<dim3(CC/128, CC/128, BB*8), 256>>>(p_B, p_C, p_kvT);

    // 7) num = phiQ @ kvT^T (batched, tensor cores)
    mma_gemm<0><<<dim3(CC/128, NN/128, BB), 256>>>(p_A, p_kvT, nullptr, nullptr, p_num,
                                                   CC, CC, (long)NN*CC, (long)CC*CC, (long)NN*CC);

    // 8) num /= (phiQ . ksum + eps)
    dendiv_kernel<<<MM/8, 256>>>(p_A, p_ksum, p_num);

    // 9) attn = num @ wo^T + b  -> bufC
    mma_gemm<0><<<dim3(CC/128, MM/128, 1), 256>>>(p_num, wo_w, wo_b, nullptr, p_C, CC, CC, 0, 0, 0);

    // 10) T1 = DyT(h + attn)
    dyt_kernel<<<MM/8, 256>>>(p_h, p_C, dyt_g, dyt_b, p_U);

    // 11) Mona 1
    zero_kernel<<<(BB*CC + 255) / 256, 256>>>(p_pool, BB*CC);
    pool_kernel<<<BB*16, 256>>>(p_U, p_pool);
    monafc_kernel<<<BB, 256>>>(p_pool, m1_w, m1_b, p_s);
    gate_kernel<<<MM*CC/256, 256>>>(p_U, p_s);          // U1 in g_U

    // 12) EDFFN (tensor cores)
    mma_gemm<0><<<dim3(DHX/128, MM/128, 1), 256>>>(p_U, we_w, we_b, nullptr, p_he, DHX, CC, 0, 0, 0);
    dwconv4_kernel<DHX, 1><<<MM*(DHX/4)/256, 256>>>(p_he, p_dwT, dw_b, p_hg);
    // U2 = 2*U1 + (hg @ wp^T + b)
    mma_gemm<1><<<dim3(CC/128, MM/128, 1), 256>>>(p_hg, wp_w, wp_b, p_U, p_A, CC, DHX, 0, 0, 0);

    // 13) T2 = DyT(U2), Mona 2
    dyt_kernel<<<MM/8, 256>>>(p_A, nullptr, dyt_g, dyt_b, p_U);
    zero_kernel<<<(BB*CC + 255) / 256, 256>>>(p_pool, BB*CC);
    pool_kernel<<<BB*16, 256>>>(p_U, p_pool);
    monafc_kernel<<<BB, 256>>>(p_pool, m2_w, m2_b, p_s);
    gate_kernel<<<MM*CC/256, 256>>>(p_U, p_s);          // Y in g_U

    // 14) out_proj + SiLU -> [B,64,H,W]
    out_proj_kernel<<<dim3(NN/64, 1, BB), 256>>>(p_U, out_proj_w, outp);
}

// round 3
// speedup vs baseline: 2.9020x; 1.3260x over previous
#include <cuda_runtime.h>
#include <cuda_fp16.h>
#include <math.h>
#include <stdint.h>

#define BB   8
#define NN   4096      // 64*64 tokens
#define CC   256
#define CIN  64
#define DHX  1024
#define MM   (BB*NN)   // 32768

// ---------------- scratch (device globals, no runtime alloc) ----------------
__device__ float  g_h   [MM*CC];
__device__ float  g_psi [MM*CC];
__device__ float  g_bufA[MM*CC];
__device__ float  g_bufB[MM*CC];
__device__ float  g_bufC[MM*CC];
__device__ float  g_num [MM*CC];
__device__ float  g_U   [MM*CC];
__device__ float  g_kvT [BB*CC*CC];
__device__ float  g_ksum[BB*CC];
__device__ float  g_pool[BB*CC];
__device__ float  g_sgt [BB*CC];
__device__ float  g_psiT[9*CC];
__device__ float  g_dwT [9*DHX];
// fp16 buffers
__device__ __half g_h16   [MM*CC];
__device__ __half g_phiQ16[MM*CC];
__device__ __half g_num16 [MM*CC];
__device__ __half g_U16   [MM*CC];
__device__ __half g_he16  [MM*DHX];
__device__ __half g_hg16  [MM*DHX];
__device__ __half g_kvT16 [BB*CC*CC];
__device__ __half g_wq16[CC*CC], g_wk16[CC*CC], g_wv16[CC*CC], g_wo16[CC*CC];
__device__ __half g_we16[DHX*CC], g_wp16[CC*DHX];

// ---------------- small device helpers ----------------
__device__ __forceinline__ float siluf(float x) { return x / (1.f + expf(-x)); }
__device__ __forceinline__ float sigm(float x)  { return 1.f / (1.f + expf(-x)); }
__device__ __forceinline__ float geluf(float x) {
    float x3 = x * x * x;
    return 0.5f * x * (1.f + tanhf(0.7978845608028654f * (x + 0.044715f * x3)));
}
__device__ __forceinline__ uint32_t tf32cvt(float f) {
    uint32_t u; asm("cvt.rna.tf32.f32 %0, %1;" : "=r"(u) : "f"(f)); return u;
}
__device__ __forceinline__ void mma_tf32(float* c, const uint32_t* a, const uint32_t* b) {
    asm volatile("mma.sync.aligned.m16n8k8.row.col.f32.tf32.tf32.f32 "
        "{%0,%1,%2,%3}, {%4,%5,%6,%7}, {%8,%9}, {%0,%1,%2,%3};"
        : "+f"(c[0]), "+f"(c[1]), "+f"(c[2]), "+f"(c[3])
        : "r"(a[0]), "r"(a[1]), "r"(a[2]), "r"(a[3]), "r"(b[0]), "r"(b[1]));
}
__device__ __forceinline__ void mma_f16(float* c, const uint32_t* a, const uint32_t* b) {
    asm volatile("mma.sync.aligned.m16n8k16.row.col.f32.f16.f16.f32 "
        "{%0,%1,%2,%3}, {%4,%5,%6,%7}, {%8,%9}, {%0,%1,%2,%3};"
        : "+f"(c[0]), "+f"(c[1]), "+f"(c[2]), "+f"(c[3])
        : "r"(a[0]), "r"(a[1]), "r"(a[2]), "r"(a[3]), "r"(b[0]), "r"(b[1]));
}

// ---------------- tiny utility kernels ----------------
__global__ void zero_kernel(float* p, int n) {
    int i = blockIdx.x * 256 + threadIdx.x;
    if (i < n) p[i] = 0.f;
}
__global__ void f2h_kernel(const float* __restrict__ in, __half* __restrict__ out, int n) {
    int i = blockIdx.x * 256 + threadIdx.x;
    if (i < n) out[i] = __float2half(in[i]);
}
__global__ void wtrans_kernel(const float* __restrict__ w, float* __restrict__ wT, int CH) {
    int i = blockIdx.x * 256 + threadIdx.x;
    if (i < CH * 9) { int c = i / 9, t = i % 9; wT[t * CH + c] = w[i]; }
}

// ---------------- in_proj: h[b,n,o] = silu( sum_c x[b,c,n] * w[o,c] ) --------
__global__ __launch_bounds__(256) void in_proj_kernel(
    const float* __restrict__ x, const float* __restrict__ w,
    float* __restrict__ h, __half* __restrict__ h16)
{
    __shared__ float Xs[64][65];
    __shared__ float Ws[64][65];
    int b = blockIdx.z, n0 = blockIdx.x * 64, o0 = blockIdx.y * 64;
    int t = threadIdx.x;
#pragma unroll
    for (int i = 0; i < 4; i++) {
        int id = t + i * 256;
        int r  = id >> 4;
        int q  = (id & 15) * 4;
        float4 vx = *(const float4*)(x + ((long)b * CIN + r) * NN + n0 + q);
        Xs[r][q] = vx.x; Xs[r][q+1] = vx.y; Xs[r][q+2] = vx.z; Xs[r][q+3] = vx.w;
        float4 vw = *(const float4*)(w + (o0 + r) * CIN + q);
        Ws[q][r] = vw.x; Ws[q+1][r] = vw.y; Ws[q+2][r] = vw.z; Ws[q+3][r] = vw.w;
    }
    __syncthreads();
    int tx = t % 16, ty = t / 16;
    float acc[4][4] = {};
#pragma unroll
    for (int c = 0; c < 64; c++) {
        float fn[4], fo[4];
#pragma unroll
        for (int i = 0; i < 4; i++) fn[i] = Xs[c][ty*4 + i];
#pragma unroll
        for (int j = 0; j < 4; j++) fo[j] = Ws[c][tx*4 + j];
#pragma unroll
        for (int i = 0; i < 4; i++)
#pragma unroll
            for (int j = 0; j < 4; j++) acc[i][j] += fn[i] * fo[j];
    }
#pragma unroll
    for (int i = 0; i < 4; i++) {
        int n = n0 + ty*4 + i;
        float4 r;
        r.x = siluf(acc[i][0]); r.y = siluf(acc[i][1]);
        r.z = siluf(acc[i][2]); r.w = siluf(acc[i][3]);
        long off = ((long)b * NN + n) * CC + o0 + tx*4;
        *(float4*)(h + off) = r;
        uint2 hq;
        *(__half2*)&hq.x = __floats2half2_rn(r.x, r.y);
        *(__half2*)&hq.y = __floats2half2_rn(r.z, r.w);
        *(uint2*)(h16 + off) = hq;
    }
}

// ---------------- depthwise 3x3 conv fp32 (psi path) ----------------
__global__ void dwconv4_kernel(const float* __restrict__ in, const float* __restrict__ cwT,
                               const float* __restrict__ cb, float* __restrict__ outp)
{
    const int CG = CC / 4;
    long i = (long)blockIdx.x * 256 + threadIdx.x;
    int c4  = (int)(i % CG);
    long pix = i / CG;
    int hw  = (int)(pix & (NN - 1));
    int b   = (int)(pix >> 12);
    int hh  = hw >> 6, ww = hw & 63;
    int c = c4 * 4;
    float4 bias4 = *(const float4*)(cb + c);
    float ax = bias4.x, ay = bias4.y, az = bias4.z, aw = bias4.w;
    const float* base = in + ((long)b * NN) * CC + c;
#pragma unroll
    for (int ky = 0; ky < 3; ky++) {
        int hy = hh + ky - 1;
        if ((unsigned)hy >= 64u) continue;
#pragma unroll
        for (int kx = 0; kx < 3; kx++) {
            int wx = ww + kx - 1;
            if ((unsigned)wx >= 64u) continue;
            float4 v = *(const float4*)(base + (long)(hy * 64 + wx) * CC);
            float4 w = *(const float4*)(cwT + (ky * 3 + kx) * CC + c);
            ax += v.x * w.x; ay += v.y * w.y; az += v.z * w.z; aw += v.w * w.w;
        }
    }
    float4 r;
    r.x = sigm(ax); r.y = sigm(ay); r.z = sigm(az); r.w = sigm(aw);
    *(float4*)(outp + i * 4) = r;
}

// ---------------- depthwise 3x3 conv fp16 io (EDFFN path, gelu) -------------
__global__ void dwconv4h_kernel(const __half* __restrict__ in, const float* __restrict__ cwT,
                                const float* __restrict__ cb, __half* __restrict__ outp)
{
    const int CG = DHX / 4;
    long i = (long)blockIdx.x * 256 + threadIdx.x;
    int c4  = (int)(i % CG);
    long pix = i / CG;
    int hw  = (int)(pix & (NN - 1));
    int b   = (int)(pix >> 12);
    int hh  = hw >> 6, ww = hw & 63;
    int c = c4 * 4;
    float4 bias4 = *(const float4*)(cb + c);
    float ax = bias4.x, ay = bias4.y, az = bias4.z, aw = bias4.w;
    const __half* base = in + ((long)b * NN) * DHX + c;
#pragma unroll
    for (int ky = 0; ky < 3; ky++) {
        int hy = hh + ky - 1;
        if ((unsigned)hy >= 64u) continue;
#pragma unroll
        for (int kx = 0; kx < 3; kx++) {
            int wx = ww + kx - 1;
            if ((unsigned)wx >= 64u) continue;
            uint2 raw = *(const uint2*)(base + (long)(hy * 64 + wx) * DHX);
            float2 v0 = __half22float2(*(__half2*)&raw.x);
            float2 v1 = __half22float2(*(__half2*)&raw.y);
            float4 w = *(const float4*)(cwT + (ky * 3 + kx) * DHX + c);
            ax += v0.x * w.x; ay += v0.y * w.y; az += v1.x * w.z; aw += v1.y * w.w;
        }
    }
    uint2 o;
    *(__half2*)&o.x = __floats2half2_rn(geluf(ax), geluf(ay));
    *(__half2*)&o.y = __floats2half2_rn(geluf(az), geluf(aw));
    *(uint2*)(outp + i * 4) = o;
}

// ---------------- FP16 MMA GEMM: Out[M,N] = A[M,K] @ B[N,K]^T (+bias)(+2aux)
// CTA 128x128, k-tile 64, 8 warps (2Mx4N), warp tile 64x32, m16n8k16.
template<int MODE, int OUTH>
__global__ __launch_bounds__(256) void hgemm(
    const __half* __restrict__ A, const __half* __restrict__ B,
    const float* __restrict__ bias, const float* __restrict__ aux,
    void* __restrict__ OutV, int Ndim, int Kdim,
    long aStrideB, long bStrideB, long oStrideB)
{
    __shared__ __half As[128][72];
    __shared__ __half Bs[128][72];
    int bz = blockIdx.z;
    A += (long)bz * aStrideB;
    B += (long)bz * bStrideB;
    float*  Outf = (float*)OutV  + (long)bz * oStrideB;
    __half* Outh = (__half*)OutV + (long)bz * oStrideB;
    int m0 = blockIdx.y * 128, n0 = blockIdx.x * 128;
    int tid = threadIdx.x, l = tid & 31, wid = tid >> 5;
    int wm = (wid >> 2) * 64, wn = (wid & 3) * 32;
    int lg = l >> 2, lt = l & 3;
    float acc[4][4][4] = {};
    for (int k0 = 0; k0 < Kdim; k0 += 64) {
#pragma unroll
        for (int i = 0; i < 4; i++) {
            int id = tid + i * 256;
            int r  = id >> 3;
            int cq = (id & 7) * 8;
            *(uint4*)&As[r][cq] = *(const uint4*)(A + (long)(m0 + r) * Kdim + k0 + cq);
            *(uint4*)&Bs[r][cq] = *(const uint4*)(B + (long)(n0 + r) * Kdim + k0 + cq);
        }
        __syncthreads();
#pragma unroll
        for (int ks = 0; ks < 4; ks++) {
            int kk = ks * 16;
            uint32_t af[4][4], bf[4][2];
#pragma unroll
            for (int mi = 0; mi < 4; mi++) {
                int rb = wm + mi * 16 + lg;
                af[mi][0] = *(const uint32_t*)&As[rb][kk + 2*lt];
                af[mi][1] = *(const uint32_t*)&As[rb + 8][kk + 2*lt];
                af[mi][2] = *(const uint32_t*)&As[rb][kk + 8 + 2*lt];
                af[mi][3] = *(const uint32_t*)&As[rb + 8][kk + 8 + 2*lt];
            }
#pragma unroll
            for (int ni = 0; ni < 4; ni++) {
                int cb = wn + ni * 8 + lg;
                bf[ni][0] = *(const uint32_t*)&Bs[cb][kk + 2*lt];
                bf[ni][1] = *(const uint32_t*)&Bs[cb][kk + 8 + 2*lt];
            }
#pragma unroll
            for (int mi = 0; mi < 4; mi++)
#pragma unroll
                for (int ni = 0; ni < 4; ni++)
                    mma_f16(acc[mi][ni], af[mi], bf[ni]);
        }
        __syncthreads();
    }
#pragma unroll
    for (int mi = 0; mi < 4; mi++) {
        int r0 = m0 + wm + mi * 16 + lg;
        int r1 = r0 + 8;
#pragma unroll
        for (int ni = 0; ni < 4; ni++) {
            int c = n0 + wn + ni * 8 + lt * 2;
            float v0 = acc[mi][ni][0], v1 = acc[mi][ni][1];
            float v2 = acc[mi][ni][2], v3 = acc[mi][ni][3];
            if (bias) { v0 += bias[c]; v1 += bias[c+1]; v2 += bias[c]; v3 += bias[c+1]; }
            if (MODE == 1) {
                v0 += 2.f * aux[(long)r0 * Ndim + c];
                v1 += 2.f * aux[(long)r0 * Ndim + c + 1];
                v2 += 2.f * aux[(long)r1 * Ndim + c];
                v3 += 2.f * aux[(long)r1 * Ndim + c + 1];
            }
            if (OUTH) {
                *(__half2*)&Outh[(long)r0 * Ndim + c] = __floats2half2_rn(v0, v1);
                *(__half2*)&Outh[(long)r1 * Ndim + c] = __floats2half2_rn(v2, v3);
            } else {
                Outf[(long)r0 * Ndim + c]     = v0;
                Outf[(long)r0 * Ndim + c + 1] = v1;
                Outf[(long)r1 * Ndim + c]     = v2;
                Outf[(long)r1 * Ndim + c + 1] = v3;
            }
        }
    }
}

// ---------------- kvT[b,d,c] = sum_n V[b,n,d] * phiK[b,n,c], TF32 MMA -------
__global__ __launch_bounds__(256) void kv_mma(
    const float* __restrict__ phiK, const float* __restrict__ V, float* __restrict__ kvT)
{
    __shared__ uint32_t Vs[32][132];
    __shared__ uint32_t Ks[32][132];
    int b = blockIdx.z >> 3, split = blockIdx.z & 7;
    int d0 = blockIdx.y * 128, c0 = blockIdx.x * 128;
    const float* Vp = V    + (long)b * NN * CC;
    const float* Kp = phiK + (long)b * NN * CC;
    int tid = threadIdx.x, wid = tid >> 5, l = tid & 31;
    int wm = (wid >> 2) * 64, wn = (wid & 3) * 32;
    int lg = l >> 2, lt = l & 3;
    float acc[4][4][4] = {};
    int nend = split * 512 + 512;
    for (int n0 = split * 512; n0 < nend; n0 += 32) {
#pragma unroll
        for (int i = 0; i < 4; i++) {
            int id = tid + i * 256;
            int nl = id >> 5;
            int q  = (id & 31) * 4;
            float4 v = *(const float4*)(Vp + (long)(n0 + nl) * CC + d0 + q);
            uint4 uv; uv.x = tf32cvt(v.x); uv.y = tf32cvt(v.y);
                      uv.z = tf32cvt(v.z); uv.w = tf32cvt(v.w);
            *(uint4*)&Vs[nl][q] = uv;
            float4 k = *(const float4*)(Kp + (long)(n0 + nl) * CC + c0 + q);
            uint4 uk; uk.x = tf32cvt(k.x); uk.y = tf32cvt(k.y);
                      uk.z = tf32cvt(k.z); uk.w = tf32cvt(k.w);
            *(uint4*)&Ks[nl][q] = uk;
        }
        __syncthreads();
#pragma unroll
        for (int ks = 0; ks < 4; ks++) {
            int kk = ks * 8;
            uint32_t af[4][4], bf[4][2];
#pragma unroll
            for (int mi = 0; mi < 4; mi++) {
                int rb = wm + mi * 16;
                af[mi][0] = Vs[kk + lt][rb + lg];
                af[mi][1] = Vs[kk + lt][rb + 8 + lg];
                af[mi][2] = Vs[kk + 4 + lt][rb + lg];
                af[mi][3] = Vs[kk + 4 + lt][rb + 8 + lg];
            }
#pragma unroll
            for (int ni = 0; ni < 4; ni++) {
                int cb = wn + ni * 8;
                bf[ni][0] = Ks[kk + lt][cb + lg];
                bf[ni][1] = Ks[kk + 4 + lt][cb + lg];
            }
#pragma unroll
            for (int mi = 0; mi < 4; mi++)
#pragma unroll
                for (int ni = 0; ni < 4; ni++)
                    mma_tf32(acc[mi][ni], af[mi], bf[ni]);
        }
        __syncthreads();
    }
    long base = (long)b * CC * CC;
#pragma unroll
    for (int mi = 0; mi < 4; mi++) {
        int r0 = d0 + wm + mi * 16 + lg;
        int r1 = r0 + 8;
#pragma unroll
        for (int ni = 0; ni < 4; ni++) {
            int c = c0 + wn + ni * 8 + lt * 2;
            atomicAdd(&kvT[base + (long)r0 * CC + c],     acc[mi][ni][0]);
            atomicAdd(&kvT[base + (long)r0 * CC + c + 1], acc[mi][ni][1]);
            atomicAdd(&kvT[base + (long)r1 * CC + c],     acc[mi][ni][2]);
            atomicAdd(&kvT[base + (long)r1 * CC + c + 1], acc[mi][ni][3]);
        }
    }
}

// ---------------- phi: pos-emb + psi gate + relu^2 --------------------------
// phiQ -> half buffer (for num GEMM + dendiv); phiK -> fp32 in place (kv+pool)
__global__ void phi_kernel(const float* __restrict__ psi,
                           const float* __restrict__ qb, float* __restrict__ kb,
                           __half* __restrict__ phiQ16)
{
    int i = blockIdx.x * 256 + threadIdx.x;
    int c   = i & 255;
    int pix = i >> 8;
    int hw  = pix & (NN - 1);
    int hh  = hw >> 6, ww = hw & 63;
    int grp = c >> 6, ci = c & 63;
    float omega = expf(-(float)ci * (9.210340371976184f / 64.f));
    float coord = (grp < 2) ? (float)ww : (float)hh;
    float arg = coord * omega;
    float posv = ((grp & 1) == 0) ? sinf(arg) : cosf(arg);
    float ps = psi[i];
    float q = ps * (qb[i] + posv); q = fmaxf(q, 0.f); phiQ16[i] = __float2half(q * q);
    float k = ps * (kb[i] + posv); k = fmaxf(k, 0.f); kb[i] = k * k;
}

// ---------------- pool: sum over 256-pixel chunks per channel (atomic) ------
__global__ void pool_kernel(const float* __restrict__ in, float* __restrict__ outp)
{
    int t = threadIdx.x;
    long base = (long)blockIdx.x * 256;
    int b = blockIdx.x >> 4;
    float acc = 0.f;
    for (int p = 0; p < 256; p++) acc += in[(base + p) * CC + t];
    atomicAdd(&outp[b * CC + t], acc);
}

// ---------------- den = phiQ . ksum + eps ; num16 = num/den -----------------
__global__ void dendiv_kernel(const __half* __restrict__ phiQ16,
                              const float* __restrict__ ksum,
                              const float* __restrict__ num, __half* __restrict__ num16)
{
    int warp = threadIdx.x >> 5, lane = threadIdx.x & 31;
    long pix = (long)blockIdx.x * 8 + warp;
    int b = (int)(pix >> 12);
    float s = 0.f;
#pragma unroll
    for (int k = 0; k < 8; k++) {
        int c = lane + k * 32;
        s += __half2float(phiQ16[pix * CC + c]) * ksum[b * CC + c];
    }
#pragma unroll
    for (int off = 16; off; off >>= 1) s += __shfl_xor_sync(0xffffffffu, s, off);
    float inv = 1.f / (s + 1e-5f);
#pragma unroll
    for (int k = 0; k < 8; k++) {
        int c = lane + k * 32;
        num16[pix * CC + c] = __float2half(num[pix * CC + c] * inv);
    }
}

// ---------------- DyT: tanh(g*(x-mu)/(std_ddof1+eps) + b) -------------------
__global__ void dyt_kernel(const float* __restrict__ in1, const float* __restrict__ in2,
                           const float* __restrict__ gam, const float* __restrict__ bet,
                           float* __restrict__ outp)
{
    int warp = threadIdx.x >> 5, lane = threadIdx.x & 31;
    long pix = (long)blockIdx.x * 8 + warp;
    float v[8];
    float s = 0.f, sq = 0.f;
#pragma unroll
    for (int k = 0; k < 8; k++) {
        int c = lane + k * 32;
        float x = in1[pix * CC + c];
        if (in2) x += in2[pix * CC + c];
        v[k] = x; s += x; sq += x * x;
    }
#pragma unroll
    for (int off = 16; off; off >>= 1) {
        s  += __shfl_xor_sync(0xffffffffu, s,  off);
        sq += __shfl_xor_sync(0xffffffffu, sq, off);
    }
    float mu  = s * (1.f / 256.f);
    float var = fmaxf(sq - 256.f * mu * mu, 0.f) * (1.f / 255.f);
    float sd  = sqrtf(var) + 1e-5f;
    float inv = 1.f / sd;
#pragma unroll
    for (int k = 0; k < 8; k++) {
        int c = lane + k * 32;
        outp[pix * CC + c] = tanhf(gam[c] * (v[k] - mu) * inv + bet[c]);
    }
}

// ---------------- Mona FC: s = sigmoid( (pool/N) @ mw^T + mb ) --------------
__global__ void monafc_kernel(const float* __restrict__ pool,
                              const float* __restrict__ mw, const float* __restrict__ mb,
                              float* __restrict__ sgate)
{
    int b = blockIdx.x, o = threadIdx.x;
    float acc = mb[o];
    const float invN = 1.f / (float)NN;
    for (int c = 0; c < CC; c++)
        acc += pool[b * CC + c] * invN * mw[o * CC + c];
    sgate[b * CC + o] = sigm(acc);
}

// ---------------- gate: x *= s[b,c]; optional fp16 copy ---------------------
__global__ void gate_kernel(float* __restrict__ p, const float* __restrict__ sgate,
                            __half* __restrict__ out16)
{
    long i = (long)blockIdx.x * 256 + threadIdx.x;
    int c = (int)(i & 255);
    long pix = i >> 8;
    int b = (int)(pix >> 12);
    float v = p[i] * sgate[b * CC + c];
    p[i] = v;
    if (out16) out16[i] = __float2half(v);
}

// ---------------- out_proj: out[b,o,n] = silu( sum_c Y[b,n,c]*w[o,c] ) ------
__global__ __launch_bounds__(256) void out_proj_kernel(
    const float* __restrict__ Y, const float* __restrict__ w, float* __restrict__ outp)
{
    __shared__ float Ys[64][65];
    __shared__ float Ws[64][65];
    int b = blockIdx.z, n0 = blockIdx.x * 64;
    int t = threadIdx.x;
    int tx = t % 16, ty = t / 16;
    float acc[4][4] = {};
    for (int ck = 0; ck < CC; ck += 64) {
#pragma unroll
        for (int i = 0; i < 4; i++) {
            int id = t + i * 256;
            int r  = id >> 4;
            int cq = (id & 15) * 4;
            float4 vy = *(const float4*)(Y + ((long)b * NN + n0 + r) * CC + ck + cq);
            Ys[cq][r] = vy.x; Ys[cq+1][r] = vy.y; Ys[cq+2][r] = vy.z; Ys[cq+3][r] = vy.w;
            float4 vw = *(const float4*)(w + r * CC + ck + cq);
            Ws[cq][r] = vw.x; Ws[cq+1][r] = vw.y; Ws[cq+2][r] = vw.z; Ws[cq+3][r] = vw.w;
        }
        __syncthreads();
#pragma unroll
        for (int c = 0; c < 64; c++) {
            float fn[4], fo[4];
#pragma unroll
            for (int i = 0; i < 4; i++) fn[i] = Ys[c][tx*4 + i];
#pragma unroll
            for (int j = 0; j < 4; j++) fo[j] = Ws[c][ty*4 + j];
#pragma unroll
            for (int j = 0; j < 4; j++)
#pragma unroll
                for (int i = 0; i < 4; i++) acc[j][i] += fo[j] * fn[i];
        }
        __syncthreads();
    }
#pragma unroll
    for (int j = 0; j < 4; j++) {
        int o = ty*4 + j;
        float4 r;
        r.x = siluf(acc[j][0]); r.y = siluf(acc[j][1]);
        r.z = siluf(acc[j][2]); r.w = siluf(acc[j][3]);
        *(float4*)(outp + ((long)b * 64 + o) * NN + n0 + tx*4) = r;
    }
}

// ---------------- launch ----------------------------------------------------
extern "C" void kernel_launch(void* const* d_in, const int* in_sizes, int n_in,
                              void* d_out, int out_size)
{
    const float* x         = (const float*)d_in[0];
    const float* in_proj_w = (const float*)d_in[1];
    const float* wq_w = (const float*)d_in[2];  const float* wq_b = (const float*)d_in[3];
    const float* wk_w = (const float*)d_in[4];  const float* wk_b = (const float*)d_in[5];
    const float* wv_w = (const float*)d_in[6];  const float* wv_b = (const float*)d_in[7];
    const float* wo_w = (const float*)d_in[8];  const float* wo_b = (const float*)d_in[9];
    const float* psi_w = (const float*)d_in[10]; const float* psi_b = (const float*)d_in[11];
    const float* dyt_g = (const float*)d_in[12]; const float* dyt_b = (const float*)d_in[13];
    const float* m1_w = (const float*)d_in[14]; const float* m1_b = (const float*)d_in[15];
    const float* m2_w = (const float*)d_in[16]; const float* m2_b = (const float*)d_in[17];
    const float* we_w = (const float*)d_in[18]; const float* we_b = (const float*)d_in[19];
    const float* dw_w = (const float*)d_in[20]; const float* dw_b = (const float*)d_in[21];
    const float* wp_w = (const float*)d_in[22]; const float* wp_b = (const float*)d_in[23];
    const float* out_proj_w = (const float*)d_in[24];
    float* outp = (float*)d_out;

    float *p_h, *p_psi, *p_A, *p_B, *p_C, *p_num, *p_U;
    float *p_kvT, *p_ksum, *p_pool, *p_s, *p_psiT, *p_dwT;
    __half *p_h16, *p_phiQ16, *p_num16, *p_U16, *p_he16, *p_hg16, *p_kvT16;
    __half *p_wq16, *p_wk16, *p_wv16, *p_wo16, *p_we16, *p_wp16;
    cudaGetSymbolAddress((void**)&p_h,    g_h);
    cudaGetSymbolAddress((void**)&p_psi,  g_psi);
    cudaGetSymbolAddress((void**)&p_A,    g_bufA);
    cudaGetSymbolAddress((void**)&p_B,    g_bufB);
    cudaGetSymbolAddress((void**)&p_C,    g_bufC);
    cudaGetSymbolAddress((void**)&p_num,  g_num);
    cudaGetSymbolAddress((void**)&p_U,    g_U);
    cudaGetSymbolAddress((void**)&p_kvT,  g_kvT);
    cudaGetSymbolAddress((void**)&p_ksum, g_ksum);
    cudaGetSymbolAddress((void**)&p_pool, g_pool);
    cudaGetSymbolAddress((void**)&p_s,    g_sgt);
    cudaGetSymbolAddress((void**)&p_psiT, g_psiT);
    cudaGetSymbolAddress((void**)&p_dwT,  g_dwT);
    cudaGetSymbolAddress((void**)&p_h16,    g_h16);
    cudaGetSymbolAddress((void**)&p_phiQ16, g_phiQ16);
    cudaGetSymbolAddress((void**)&p_num16,  g_num16);
    cudaGetSymbolAddress((void**)&p_U16,    g_U16);
    cudaGetSymbolAddress((void**)&p_he16,   g_he16);
    cudaGetSymbolAddress((void**)&p_hg16,   g_hg16);
    cudaGetSymbolAddress((void**)&p_kvT16,  g_kvT16);
    cudaGetSymbolAddress((void**)&p_wq16, g_wq16);
    cudaGetSymbolAddress((void**)&p_wk16, g_wk16);
    cudaGetSymbolAddress((void**)&p_wv16, g_wv16);
    cudaGetSymbolAddress((void**)&p_wo16, g_wo16);
    cudaGetSymbolAddress((void**)&p_we16, g_we16);
    cudaGetSymbolAddress((void**)&p_wp16, g_wp16);

    // prep: zero accumulators, transpose dwconv weights, fp16 weight copies
    zero_kernel<<<(BB*CC*CC + 255) / 256, 256>>>(p_kvT, BB*CC*CC);
    zero_kernel<<<(BB*CC + 255) / 256, 256>>>(p_ksum, BB*CC);
    wtrans_kernel<<<(CC*9 + 255) / 256, 256>>>(psi_w, p_psiT, CC);
    wtrans_kernel<<<(DHX*9 + 255) / 256, 256>>>(dw_w, p_dwT, DHX);
    f2h_kernel<<<(CC*CC + 255) / 256, 256>>>(wq_w, p_wq16, CC*CC);
    f2h_kernel<<<(CC*CC + 255) / 256, 256>>>(wk_w, p_wk16, CC*CC);
    f2h_kernel<<<(CC*CC + 255) / 256, 256>>>(wv_w, p_wv16, CC*CC);
    f2h_kernel<<<(CC*CC + 255) / 256, 256>>>(wo_w, p_wo16, CC*CC);
    f2h_kernel<<<(DHX*CC + 255) / 256, 256>>>(we_w, p_we16, DHX*CC);
    f2h_kernel<<<(CC*DHX + 255) / 256, 256>>>(wp_w, p_wp16, CC*DHX);

    // 1) in_proj + SiLU -> h (fp32 + fp16)
    in_proj_kernel<<<dim3(NN/64, CC/64, BB), 256>>>(x, in_proj_w, p_h, p_h16);

    // 2) psi = sigmoid(dwconv3x3(h))
    dwconv4_kernel<<<MM*(CC/4)/256, 256>>>(p_h, p_psiT, psi_b, p_psi);

    // 3) Q/K/V projections (fp16 tensor cores)
    hgemm<0,0><<<dim3(CC/128, MM/128, 1), 256>>>(p_h16, p_wq16, wq_b, nullptr, p_A, CC, CC, 0, 0, 0);
    hgemm<0,0><<<dim3(CC/128, MM/128, 1), 256>>>(p_h16, p_wk16, wk_b, nullptr, p_B, CC, CC, 0, 0, 0);
    hgemm<0,0><<<dim3(CC/128, MM/128, 1), 256>>>(p_h16, p_wv16, wv_b, nullptr, p_C, CC, CC, 0, 0, 0);

    // 4) phiQ (fp16), phiK (fp32 in place)
    phi_kernel<<<MM*CC/256, 256>>>(p_psi, p_A, p_B, p_phiQ16);

    // 5) ksum = sum_n phiK
    pool_kernel<<<BB*16, 256>>>(p_B, p_ksum);

    // 6) kvT (TF32, split-K atomics) then fp16 copy
    kv_mma<<<dim3(CC/128, CC/128, BB*8), 256>>>(p_B, p_C, p_kvT);
    f2h_kernel<<<(BB*CC*CC + 255) / 256, 256>>>(p_kvT, p_kvT16, BB*CC*CC);

    // 7) num = phiQ @ kvT^T (batched fp16)
    hgemm<0,0><<<dim3(CC/128, NN/128, BB), 256>>>(p_phiQ16, p_kvT16, nullptr, nullptr, p_num,
                                                  CC, CC, (long)NN*CC, (long)CC*CC, (long)NN*CC);

    // 8) num16 = num / (phiQ . ksum + eps)
    dendiv_kernel<<<MM/8, 256>>>(p_phiQ16, p_ksum, p_num, p_num16);

    // 9) attn = num @ wo^T + b -> bufC (fp32)
    hgemm<0,0><<<dim3(CC/128, MM/128, 1), 256>>>(p_num16, p_wo16, wo_b, nullptr, p_C, CC, CC, 0, 0, 0);

    // 10) T1 = DyT(h + attn)
    dyt_kernel<<<MM/8, 256>>>(p_h, p_C, dyt_g, dyt_b, p_U);

    // 11) Mona 1 (gate writes U fp32 + U16)
    zero_kernel<<<(BB*CC + 255) / 256, 256>>>(p_pool, BB*CC);
    pool_kernel<<<BB*16, 256>>>(p_U, p_pool);
    monafc_kernel<<<BB, 256>>>(p_pool, m1_w, m1_b, p_s);
    gate_kernel<<<MM*CC/256, 256>>>(p_U, p_s, p_U16);

    // 12) EDFFN: we (fp16 out) -> dwconv gelu (fp16 io) -> wp (+2*U1)
    hgemm<0,1><<<dim3(DHX/128, MM/128, 1), 256>>>(p_U16, p_we16, we_b, nullptr, p_he16, DHX, CC, 0, 0, 0);
    dwconv4h_kernel<<<MM*(DHX/4)/256, 256>>>(p_he16, p_dwT, dw_b, p_hg16);
    hgemm<1,0><<<dim3(CC/128, MM/128, 1), 256>>>(p_hg16, p_wp16, wp_b, p_U, p_A, CC, DHX, 0, 0, 0);

    // 13) T2 = DyT(U2), Mona 2
    dyt_kernel<<<MM/8, 256>>>(p_A, nullptr, dyt_g, dyt_b, p_U);
    zero_kernel<<<(BB*CC + 255) / 256, 256>>>(p_pool, BB*CC);
    pool_kernel<<<BB*16, 256>>>(p_U, p_pool);
    monafc_kernel<<<BB, 256>>>(p_pool, m2_w, m2_b, p_s);
    gate_kernel<<<MM*CC/256, 256>>>(p_U, p_s, nullptr);

    // 14) out_proj + SiLU -> [B,64,H,W]
    out_proj_kernel<<<dim3(NN/64, 1, BB), 256>>>(p_U, out_proj_w, outp);
}